// round 15
// baseline (speedup 1.0000x reference)
#include <cuda_runtime.h>
#include <cuda_bf16.h>
#include <cstdint>

// ---------------- problem constants ----------------
constexpr int NN  = 32768;   // nodes
constexpr int HH  = 128;     // hidden
constexpr int RR  = 16;      // rules
constexpr int OUTC = 40;     // output classes
constexpr float EPS = 1e-5f;
constexpr int KTOT = RR * HH;   // 2048

// k_layer smem word offsets (M=64 tile, 2 CTAs/SM)
constexpr int L_OFF_BC = 0;                    // bc: 16*128 = 2048 w
constexpr int L_OFF_W  = 2048;                 // w: 64*17 = 1088 w
constexpr int L_OFF_A  = 3136;                 // A hi/lo bf16 (cen/siw overlay pre-split)
constexpr int L_AW     = 68;                   // A row stride (64 data words + 4 pad; 4g+tig banks)
constexpr int L_A_TW   = 64 * L_AW;            // 4352 w per A tile
constexpr int L_OFF_B  = L_OFF_A + 2 * L_A_TW; // 11840 (hraw 64x128 overlay in prologue)
constexpr int L_BW     = 20;                   // B row stride (16 data words + 4 pad; 20g+tig banks ok)
constexpr int L_B_TW   = 128 * L_BW;           // 2560 w per digit tile
constexpr int L_B_SW   = 2 * L_B_TW;           // 5120 w per stage (hi+lo)
constexpr int L_SMEM_WORDS = L_OFF_B + 2 * L_B_SW;  // 22080
constexpr int L_SMEM_BYTES = L_SMEM_WORDS * 4;      // 88320

// k_gemm_in smem layout
constexpr int GW      = 68;
constexpr int G_TW    = 128 * GW;
constexpr int GIN_WORDS = 4 * G_TW;
constexpr int GIN_BYTES = GIN_WORDS * 4;

// ---------------- device scratch ----------------
__device__ __align__(16) float g_h[NN * HH];
__device__ __align__(16) float g_msg[NN * HH];
__device__ __align__(16) float g_a[NN * HH];
__device__ __align__(16) __nv_bfloat16 g_BtHi[3 * HH * KTOT];
__device__ __align__(16) __nv_bfloat16 g_BtLo[3 * HH * KTOT];
__device__ __align__(16) __nv_bfloat16 g_WinHi[HH * HH];
__device__ __align__(16) __nv_bfloat16 g_WinLo[HH * HH];
__device__ int   g_deg[NN];
__device__ int   g_cursor[NN];
__device__ int   g_rowptr[NN + 1];
__device__ int   g_col[1 << 20];
__device__ float g_sumS[2][HH];
__device__ float g_sumqS[2][HH];

// ---------------- helpers ----------------
__device__ __forceinline__ uint32_t smem_u32(const void* p) {
    uint32_t a;
    asm("{ .reg .u64 t; cvta.to.shared.u64 t, %1; cvt.u32.u64 %0, t; }" : "=r"(a) : "l"(p));
    return a;
}
__device__ __forceinline__ void cp_async16(uint32_t dst, const void* src) {
    asm volatile("cp.async.cg.shared.global [%0], [%1], 16;" :: "r"(dst), "l"(src));
}
__device__ __forceinline__ void cp_commit() {
    asm volatile("cp.async.commit_group;");
}
__device__ __forceinline__ void cp_wait0() {
    asm volatile("cp.async.wait_group 0;" ::: "memory");
}
__device__ __forceinline__ void sts_v2u(uint32_t addr, uint32_t a, uint32_t b) {
    asm volatile("st.shared.v2.b32 [%0], {%1, %2};" :: "r"(addr), "r"(a), "r"(b) : "memory");
}
__device__ __forceinline__ uint32_t pack_bf2(float a, float b) {
    __nv_bfloat162 t;
    t.x = __float2bfloat16(a);
    t.y = __float2bfloat16(b);
    return *(uint32_t*)&t;
}
__device__ __forceinline__ void mma_bf16(float* d, const uint32_t* a, const uint32_t* b) {
    asm volatile(
        "mma.sync.aligned.m16n8k16.row.col.f32.bf16.bf16.f32 "
        "{%0, %1, %2, %3}, {%4, %5, %6, %7}, {%8, %9}, {%0, %1, %2, %3};"
        : "+f"(d[0]), "+f"(d[1]), "+f"(d[2]), "+f"(d[3])
        : "r"(a[0]), "r"(a[1]), "r"(a[2]), "r"(a[3]), "r"(b[0]), "r"(b[1]));
}

// ---------------- CSR build (+ initial BN stat zero) ----------------
__global__ void k_zero_csr() {
    int i = blockIdx.x * blockDim.x + threadIdx.x;
    if (i < NN) { g_deg[i] = 0; g_cursor[i] = 0; }
    if (blockIdx.x == 0 && threadIdx.x < HH) {
        g_sumS[0][threadIdx.x] = 0.f; g_sumqS[0][threadIdx.x] = 0.f;
        g_sumS[1][threadIdx.x] = 0.f; g_sumqS[1][threadIdx.x] = 0.f;
    }
}

__global__ void k_count(const int* __restrict__ dst, int E) {
    int e = blockIdx.x * blockDim.x + threadIdx.x;
    if (e < E) atomicAdd(&g_deg[dst[e]], 1);
}

__global__ void k_scan(int E) {
    __shared__ int sh[1024];
    int t = threadIdx.x;
    int cnt[32];
    int tot = 0;
    #pragma unroll
    for (int i = 0; i < 32; i++) { cnt[i] = g_deg[t * 32 + i]; tot += cnt[i]; }
    sh[t] = tot;
    __syncthreads();
    for (int off = 1; off < 1024; off <<= 1) {
        int v = (t >= off) ? sh[t - off] : 0;
        __syncthreads();
        sh[t] += v;
        __syncthreads();
    }
    int base = sh[t] - tot;
    #pragma unroll
    for (int i = 0; i < 32; i++) { g_rowptr[t * 32 + i] = base; base += cnt[i]; }
    if (t == 1023) g_rowptr[NN] = E;
}

__global__ void k_fill(const int* __restrict__ src, const int* __restrict__ dst, int E) {
    int e = blockIdx.x * blockDim.x + threadIdx.x;
    if (e < E) {
        int d = dst[e];
        int p = atomicAdd(&g_cursor[d], 1);
        g_col[g_rowptr[d] + p] = src[e];
    }
}

// ---------------- combined weight preprocessing: Wc^T + W_in^T hi/lo splits ----------------
__global__ void k_transAll(const float* __restrict__ Wc, const float* __restrict__ Win) {
    int idx = blockIdx.x * blockDim.x + threadIdx.x;
    if (idx < 3 * KTOT * HH) {
        int l = idx >> 18;
        int rem = idx & 262143;
        int k = rem >> 7;
        int o = rem & 127;
        float v = Wc[idx];
        __nv_bfloat16 hi = __float2bfloat16(v);
        __nv_bfloat16 lo = __float2bfloat16(v - __bfloat162float(hi));
        size_t di = (size_t)l * 262144 + (size_t)o * KTOT + k;
        g_BtHi[di] = hi;
        g_BtLo[di] = lo;
    } else {
        int j = idx - 3 * KTOT * HH;
        int k = j >> 7;
        int o = j & 127;
        float v = Win[j];
        __nv_bfloat16 hi = __float2bfloat16(v);
        __nv_bfloat16 lo = __float2bfloat16(v - __bfloat162float(hi));
        g_WinHi[o * HH + k] = hi;
        g_WinLo[o * HH + k] = lo;
    }
}

// ---------------- input GEMM (3xBF16 MMA): g_h = relu(x @ W_in + b_in), K=128 ----------------
__global__ __launch_bounds__(256, 1) void k_gemm_in(
    const float* __restrict__ x, const float* __restrict__ bias)
{
    extern __shared__ float sm[];
    const uint32_t smBase = smem_u32(sm);
    uint32_t* SW = (uint32_t*)sm;

    const int tid  = threadIdx.x;
    const int m0   = blockIdx.x * 128;
    const int warp = tid >> 5, lane = tid & 31;
    const int mwarp = warp >> 2;
    const int nwarp = warp & 3;
    const int g   = lane >> 2;
    const int tig = lane & 3;

    #pragma unroll
    for (int i = 0; i < 16; i++) {
        int t = tid + i * 256;
        int row = t >> 5, seg = t & 31;
        float4 v = *(const float4*)&x[(size_t)(m0 + row) * HH + seg * 4];
        __nv_bfloat16 h0 = __float2bfloat16(v.x), h1 = __float2bfloat16(v.y);
        __nv_bfloat16 h2 = __float2bfloat16(v.z), h3 = __float2bfloat16(v.w);
        uint32_t hw0, hw1;
        { __nv_bfloat162 q; q.x = h0; q.y = h1; hw0 = *(uint32_t*)&q; }
        { __nv_bfloat162 q; q.x = h2; q.y = h3; hw1 = *(uint32_t*)&q; }
        uint32_t dst = smBase + (row * GW + seg * 2) * 4;
        sts_v2u(dst, hw0, hw1);
        uint32_t lw0 = pack_bf2(v.x - __bfloat162float(h0), v.y - __bfloat162float(h1));
        uint32_t lw1 = pack_bf2(v.z - __bfloat162float(h2), v.w - __bfloat162float(h3));
        sts_v2u(dst + G_TW * 4, lw0, lw1);
    }
    const uint4* bhp = (const uint4*)g_WinHi;
    const uint4* blp = (const uint4*)g_WinLo;
    #pragma unroll
    for (int i = 0; i < 8; i++) {
        int t = tid + i * 256;
        int row = t >> 4, seg = t & 15;
        uint4 vh = bhp[t];
        uint4 vl = blp[t];
        *(uint4*)((char*)sm + ((2 * G_TW + row * GW + seg * 4) * 4)) = vh;
        *(uint4*)((char*)sm + ((3 * G_TW + row * GW + seg * 4) * 4)) = vl;
    }
    __syncthreads();

    float acc[4][4][4];
    #pragma unroll
    for (int mi = 0; mi < 4; mi++)
        #pragma unroll
        for (int ni = 0; ni < 4; ni++)
            #pragma unroll
            for (int v = 0; v < 4; v++) acc[mi][ni][v] = 0.f;

    const uint32_t* Ah = SW;
    const uint32_t* Al = Ah + G_TW;
    const uint32_t* Bh = Ah + 2 * G_TW;
    const uint32_t* Bl = Ah + 3 * G_TW;

    #pragma unroll
    for (int ks = 0; ks < 8; ks++) {
        const int kw = ks * 8 + tig;
        uint32_t bh[4][2], bl[4][2];
        #pragma unroll
        for (int ni = 0; ni < 4; ni++) {
            int n = nwarp * 32 + ni * 8 + g;
            bh[ni][0] = Bh[n * GW + kw];
            bh[ni][1] = Bh[n * GW + kw + 4];
            bl[ni][0] = Bl[n * GW + kw];
            bl[ni][1] = Bl[n * GW + kw + 4];
        }
        #pragma unroll
        for (int mi = 0; mi < 4; mi++) {
            int m = mwarp * 64 + mi * 16;
            uint32_t ah[4], al[4];
            ah[0] = Ah[(m + g)     * GW + kw];
            ah[1] = Ah[(m + g + 8) * GW + kw];
            ah[2] = Ah[(m + g)     * GW + kw + 4];
            ah[3] = Ah[(m + g + 8) * GW + kw + 4];
            al[0] = Al[(m + g)     * GW + kw];
            al[1] = Al[(m + g + 8) * GW + kw];
            al[2] = Al[(m + g)     * GW + kw + 4];
            al[3] = Al[(m + g + 8) * GW + kw + 4];
            #pragma unroll
            for (int ni = 0; ni < 4; ni++) {
                mma_bf16(acc[mi][ni], ah, bh[ni]);
                mma_bf16(acc[mi][ni], al, bh[ni]);
                mma_bf16(acc[mi][ni], ah, bl[ni]);
            }
        }
    }

    #pragma unroll
    for (int mi = 0; mi < 4; mi++) {
        #pragma unroll
        for (int ni = 0; ni < 4; ni++) {
            int grow = m0 + mwarp * 64 + mi * 16 + g;
            int gcol = nwarp * 32 + ni * 8 + 2 * tig;
            float b0 = __ldg(&bias[gcol]);
            float b1 = __ldg(&bias[gcol + 1]);
            float2 v;
            v.x = fmaxf(acc[mi][ni][0] + b0, 0.f);
            v.y = fmaxf(acc[mi][ni][1] + b1, 0.f);
            *(float2*)&g_h[(size_t)grow * HH + gcol] = v;
            float2 u;
            u.x = fmaxf(acc[mi][ni][2] + b0, 0.f);
            u.y = fmaxf(acc[mi][ni][3] + b1, 0.f);
            *(float2*)&g_h[(size_t)(grow + 8) * HH + gcol] = u;
        }
    }
}

// ---------------- fused layer kernel (M=64 tile, 128 thr, 2 CTAs/SM) ----------------
// rules + rule-major 3xBF16 GEMM; warp tile 32x64 (2m x 2n warps).
__global__ __launch_bounds__(128, 2) void k_layer(
    const float* __restrict__ cen, const float* __restrict__ wid,
    const float* __restrict__ bcl, int layer)
{
    extern __shared__ float sm[];
    const uint32_t smBase = smem_u32(sm);
    uint32_t* SW = (uint32_t*)sm;

    const __nv_bfloat16* __restrict__ BtHi = g_BtHi + (size_t)layer * (HH * KTOT);
    const __nv_bfloat16* __restrict__ BtLo = g_BtLo + (size_t)layer * (HH * KTOT);
    const int tid  = threadIdx.x;
    const int m0   = blockIdx.x * 64;
    const int warp = tid >> 5, lane = tid & 31;
    const int mwarp = warp >> 1;          // 0..1 (32 rows each)
    const int nwarp = warp & 1;           // 0..1 (64 cols each)
    const int g   = lane >> 2;            // 0..7
    const int tig = lane & 3;             // 0..3

    // ---- load bc, cen, siw (cen/siw overlay A region pre-split) ----
    for (int i = tid; i < RR * HH; i += 128) {
        sm[L_OFF_BC + i] = bcl[i];
        sm[L_OFF_A + i] = cen[i];
        float w = wid[i];
        sm[L_OFF_A + 2048 + i] = 1.f / (2.f * w * w);
    }
    // ---- h tile (64 x 128) fp32 into hraw (overlays B region) ----
    #pragma unroll
    for (int i = 0; i < 16; i++) {
        int t = tid + i * 128;          // 0..2047 float4 units
        int row = t >> 5, q = t & 31;
        *(float4*)&sm[L_OFF_B + row * 128 + q * 4] =
            *(const float4*)&g_h[(size_t)(m0 + row) * HH + q * 4];
    }
    __syncthreads();

    // ---- rules: each warp handles 16 nodes (4 warps x 16 = 64) ----
    {
        const float* hraw = sm + L_OFF_B;
        const float* scen = sm + L_OFF_A;
        const float* ssiw = sm + L_OFF_A + 2048;
        for (int i = 0; i < 16; i++) {
            int node = warp * 16 + i;
            float4 h4 = *(const float4*)&hraw[node * 128 + lane * 4];
            float sr[16];
            #pragma unroll
            for (int r = 0; r < 16; r++) {
                float4 c  = *(const float4*)&scen[r * 128 + lane * 4];
                float4 iw = *(const float4*)&ssiw[r * 128 + lane * 4];
                float dx = h4.x - c.x, dy = h4.y - c.y, dz = h4.z - c.z, dw = h4.w - c.w;
                float p = dx * dx * iw.x + dy * dy * iw.y + dz * dz * iw.z + dw * dw * iw.w;
                #pragma unroll
                for (int o = 16; o; o >>= 1) p += __shfl_xor_sync(0xffffffffu, p, o);
                sr[r] = -p * (1.f / 128.f);
            }
            float m = sr[0];
            #pragma unroll
            for (int r = 1; r < 16; r++) m = fmaxf(m, sr[r]);
            float s = 0.f;
            #pragma unroll
            for (int r = 0; r < 16; r++) { sr[r] = expf(sr[r] - m); s += sr[r]; }
            float inv = 1.f / s;
            #pragma unroll
            for (int r = 0; r < 16; r++) {
                if (lane == r) sm[L_OFF_W + node * 17 + r] = sr[r] * inv;
            }
        }
    }
    __syncthreads();

    // ---- split h -> A hi/lo bf16 tiles (overwrites cen/siw region) ----
    #pragma unroll
    for (int i = 0; i < 16; i++) {
        int t = tid + i * 128;          // 2048 float4 units: 64 rows x 32 segs
        int row = t >> 5, seg = t & 31;
        float4 v = *(const float4*)&sm[L_OFF_B + row * 128 + seg * 4];
        __nv_bfloat16 h0 = __float2bfloat16(v.x), h1 = __float2bfloat16(v.y);
        __nv_bfloat16 h2 = __float2bfloat16(v.z), h3 = __float2bfloat16(v.w);
        uint32_t hw0, hw1;
        { __nv_bfloat162 q; q.x = h0; q.y = h1; hw0 = *(uint32_t*)&q; }
        { __nv_bfloat162 q; q.x = h2; q.y = h3; hw1 = *(uint32_t*)&q; }
        uint32_t dst = smBase + (L_OFF_A + row * L_AW + seg * 2) * 4;
        sts_v2u(dst, hw0, hw1);
        uint32_t lw0 = pack_bf2(v.x - __bfloat162float(h0), v.y - __bfloat162float(h1));
        uint32_t lw1 = pack_bf2(v.z - __bfloat162float(h2), v.w - __bfloat162float(h3));
        sts_v2u(dst + L_A_TW * 4, lw0, lw1);
    }
    __syncthreads();

    // ---- accumulators: warp tile 32x64 -> mi 0..1, ni 0..7 ----
    float accT[2][8][4], accR[2][8][4];
    #pragma unroll
    for (int mi = 0; mi < 2; mi++)
        #pragma unroll
        for (int ni = 0; ni < 8; ni++)
            #pragma unroll
            for (int v = 0; v < 4; v++) { accT[mi][ni][v] = 0.f; accR[mi][ni][v] = 0.f; }

    // B cp.async: chunk c -> rule r=c>>2, quarter q=c&3 -> k0 = r*128 + q*32
    // per chunk: 128 rows x 2 digits x 16 data words = 16KB = 1024 cp16; 128 thr x 8
    auto cpB = [&](int c, int stage) {
        const int k0 = (c >> 2) * 128 + (c & 3) * 32;
        #pragma unroll
        for (int i = 0; i < 8; i++) {
            int t = tid + i * 128;          // 0..1023
            int digit = t >> 9;             // 0 = hi, 1 = lo
            int row   = (t >> 2) & 127;
            int pc    = t & 3;              // 16B piece (8 bf16)
            size_t gsrc = (size_t)row * KTOT + k0 + pc * 8;
            uint32_t dst = smBase +
                (L_OFF_B + stage * L_B_SW + digit * L_B_TW + row * L_BW + pc * 4) * 4;
            cp_async16(dst, digit ? (const void*)&BtLo[gsrc] : (const void*)&BtHi[gsrc]);
        }
        cp_commit();
    };

    cpB(0, 0);

    for (int c = 0; c < 64; ++c) {
        const int s = c & 1;
        cp_wait0();
        __syncthreads();
        if (c + 1 < 64) cpB(c + 1, s ^ 1);

        const uint32_t* Ah = SW + L_OFF_A;
        const uint32_t* Al = Ah + L_A_TW;
        const uint32_t* Bh = SW + L_OFF_B + s * L_B_SW;
        const uint32_t* Bl = Bh + L_B_TW;
        const int abase = (c & 3) * 16;    // word offset into 64-data-word A row

        #pragma unroll
        for (int ks = 0; ks < 2; ks++) {
            const int kwB = ks * 8 + tig;
            const int kwA = abase + kwB;
            uint32_t bh[8][2], bl[8][2];
            #pragma unroll
            for (int ni = 0; ni < 8; ni++) {
                int n = nwarp * 64 + ni * 8 + g;
                bh[ni][0] = Bh[n * L_BW + kwB];
                bh[ni][1] = Bh[n * L_BW + kwB + 4];
                bl[ni][0] = Bl[n * L_BW + kwB];
                bl[ni][1] = Bl[n * L_BW + kwB + 4];
            }
            #pragma unroll
            for (int mi = 0; mi < 2; mi++) {
                int m = mwarp * 32 + mi * 16;
                uint32_t ah[4], al[4];
                ah[0] = Ah[(m + g)     * L_AW + kwA];
                ah[1] = Ah[(m + g + 8) * L_AW + kwA];
                ah[2] = Ah[(m + g)     * L_AW + kwA + 4];
                ah[3] = Ah[(m + g + 8) * L_AW + kwA + 4];
                al[0] = Al[(m + g)     * L_AW + kwA];
                al[1] = Al[(m + g + 8) * L_AW + kwA];
                al[2] = Al[(m + g)     * L_AW + kwA + 4];
                al[3] = Al[(m + g + 8) * L_AW + kwA + 4];
                #pragma unroll
                for (int ni = 0; ni < 8; ni++) {
                    mma_bf16(accR[mi][ni], ah, bh[ni]);
                    mma_bf16(accR[mi][ni], al, bh[ni]);
                    mma_bf16(accR[mi][ni], ah, bl[ni]);
                }
            }
        }

        if ((c & 3) == 3) {
            const int r = c >> 2;
            #pragma unroll
            for (int mi = 0; mi < 2; mi++) {
                int mrow = mwarp * 32 + mi * 16 + g;
                float w0 = sm[L_OFF_W + mrow * 17 + r];
                float w1 = sm[L_OFF_W + (mrow + 8) * 17 + r];
                #pragma unroll
                for (int ni = 0; ni < 8; ni++) {
                    int col = nwarp * 64 + ni * 8 + 2 * tig;
                    float bc0 = sm[L_OFF_BC + r * 128 + col];
                    float bc1 = sm[L_OFF_BC + r * 128 + col + 1];
                    accT[mi][ni][0] += w0 * (accR[mi][ni][0] + bc0);
                    accT[mi][ni][1] += w0 * (accR[mi][ni][1] + bc1);
                    accT[mi][ni][2] += w1 * (accR[mi][ni][2] + bc0);
                    accT[mi][ni][3] += w1 * (accR[mi][ni][3] + bc1);
                    accR[mi][ni][0] = 0.f; accR[mi][ni][1] = 0.f;
                    accR[mi][ni][2] = 0.f; accR[mi][ni][3] = 0.f;
                }
            }
        }
    }

    // ---- epilogue: pure store of msg (64 rows) ----
    #pragma unroll
    for (int mi = 0; mi < 2; mi++) {
        #pragma unroll
        for (int ni = 0; ni < 8; ni++) {
            int grow = m0 + mwarp * 32 + mi * 16 + g;
            int gcol = nwarp * 64 + ni * 8 + 2 * tig;
            float2 v; v.x = accT[mi][ni][0]; v.y = accT[mi][ni][1];
            *(float2*)&g_msg[(size_t)grow * HH + gcol] = v;
            float2 u; u.x = accT[mi][ni][2]; u.y = accT[mi][ni][3];
            *(float2*)&g_msg[(size_t)(grow + 8) * HH + gcol] = u;
        }
    }
}

// ---------------- edge aggregation (CSR gather, unrolled x4 for MLP) ----------------
__global__ __launch_bounds__(256) void k_aggregate() {
    const int warp = threadIdx.x >> 5, lane = threadIdx.x & 31;
    const int n = blockIdx.x * 8 + warp;
    int s0 = g_rowptr[n], s1 = g_rowptr[n + 1];
    float4 acc0 = {0.f, 0.f, 0.f, 0.f};
    float4 acc1 = {0.f, 0.f, 0.f, 0.f};
    const float4* mp = (const float4*)g_msg;
    int j = s0;
    for (; j + 3 < s1; j += 4) {
        int i0 = g_col[j],     i1 = g_col[j + 1];
        int i2 = g_col[j + 2], i3 = g_col[j + 3];
        float4 v0 = mp[i0 * 32 + lane];
        float4 v1 = mp[i1 * 32 + lane];
        float4 v2 = mp[i2 * 32 + lane];
        float4 v3 = mp[i3 * 32 + lane];
        acc0.x += v0.x + v1.x; acc0.y += v0.y + v1.y;
        acc0.z += v0.z + v1.z; acc0.w += v0.w + v1.w;
        acc1.x += v2.x + v3.x; acc1.y += v2.y + v3.y;
        acc1.z += v2.z + v3.z; acc1.w += v2.w + v3.w;
    }
    for (; j < s1; j++) {
        int src = g_col[j];
        float4 v = mp[src * 32 + lane];
        acc0.x += v.x; acc0.y += v.y; acc0.z += v.z; acc0.w += v.w;
    }
    int d = s1 - s0;
    float invd = 1.f / (float)(d > 0 ? d : 1);
    float4 a;
    a.x = fmaxf((acc0.x + acc1.x) * invd, 0.f);
    a.y = fmaxf((acc0.y + acc1.y) * invd, 0.f);
    a.z = fmaxf((acc0.z + acc1.z) * invd, 0.f);
    a.w = fmaxf((acc0.w + acc1.w) * invd, 0.f);
    *(float4*)&g_a[(size_t)n * HH + lane * 4] = a;
}

// ---------------- BN stats ----------------
__global__ __launch_bounds__(128) void k_bn_stats(int parity) {
    const int t = threadIdx.x;
    float s = 0.f, q = 0.f;
    for (int row = blockIdx.x; row < NN; row += gridDim.x) {
        float v = g_a[row * HH + t];
        s += v; q += v * v;
    }
    atomicAdd(&g_sumS[parity][t], s);
    atomicAdd(&g_sumqS[parity][t], q);
}

// ---------------- bn_apply: vectorized float4, zeroes next parity buffer ----------------
__global__ __launch_bounds__(256) void k_bn_apply(
    const float* __restrict__ gamma, const float* __restrict__ beta, int parity)
{
    __shared__ float smu[HH], ssc[HH], sbb[HH];
    const int tid = threadIdx.x;
    if (tid < 128) {
        const float inv_n = 1.f / (float)NN;
        float mu  = g_sumS[parity][tid] * inv_n;
        float var = g_sumqS[parity][tid] * inv_n - mu * mu;
        smu[tid] = mu;
        ssc[tid] = gamma[tid] * rsqrtf(var + EPS);
        sbb[tid] = beta[tid];
        if (blockIdx.x == 0) {
            g_sumS[parity ^ 1][tid] = 0.f;
            g_sumqS[parity ^ 1][tid] = 0.f;
        }
    }
    __syncthreads();
    const int lane = tid & 31;
    const int wrp  = tid >> 5;
    const int f = lane * 4;
    float4 mu4 = *(float4*)&smu[f];
    float4 sc4 = *(float4*)&ssc[f];
    float4 bb4 = *(float4*)&sbb[f];
    for (int row = blockIdx.x * 8 + wrp; row < NN; row += gridDim.x * 8) {
        size_t gi = (size_t)row * HH + f;
        float4 h4 = *(float4*)&g_h[gi];
        float4 a4 = *(const float4*)&g_a[gi];
        h4.x += (a4.x - mu4.x) * sc4.x + bb4.x;
        h4.y += (a4.y - mu4.y) * sc4.y + bb4.y;
        h4.z += (a4.z - mu4.z) * sc4.z + bb4.z;
        h4.w += (a4.w - mu4.w) * sc4.w + bb4.w;
        *(float4*)&g_h[gi] = h4;
    }
}

// ---------------- head: out = softmax(h @ W_head + b_head) ----------------
__global__ __launch_bounds__(128) void k_head(
    const float* __restrict__ W, const float* __restrict__ b, float* __restrict__ out)
{
    __shared__ float hs[HH];
    __shared__ float lg[OUTC];
    __shared__ float red[2];
    const int t = threadIdx.x;
    const int n = blockIdx.x;
    hs[t] = g_h[n * HH + t];
    __syncthreads();
    if (t < OUTC) {
        float acc = b[t];
        #pragma unroll 8
        for (int k = 0; k < HH; k++) acc += hs[k] * W[k * OUTC + t];
        lg[t] = acc;
    }
    __syncthreads();
    if (t == 0) {
        float m = lg[0];
        for (int i = 1; i < OUTC; i++) m = fmaxf(m, lg[i]);
        red[0] = m;
    }
    __syncthreads();
    if (t < OUTC) lg[t] = expf(lg[t] - red[0]);
    __syncthreads();
    if (t == 0) {
        float s = 0.f;
        for (int i = 0; i < OUTC; i++) s += lg[i];
        red[1] = 1.f / s;
    }
    __syncthreads();
    if (t < OUTC) out[n * OUTC + t] = lg[t] * red[1];
}

// ---------------- launch ----------------
extern "C" void kernel_launch(void* const* d_in, const int* in_sizes, int n_in,
                              void* d_out, int out_size)
{
    const float* x      = (const float*)d_in[0];
    const int*   ei     = (const int*)d_in[1];
    const float* W_in   = (const float*)d_in[2];
    const float* b_in   = (const float*)d_in[3];
    const float* cen    = (const float*)d_in[4];
    const float* wid    = (const float*)d_in[5];
    const float* Wc     = (const float*)d_in[6];
    const float* bc     = (const float*)d_in[7];
    const float* gamma  = (const float*)d_in[8];
    const float* beta   = (const float*)d_in[9];
    const float* W_head = (const float*)d_in[10];
    const float* b_head = (const float*)d_in[11];
    float* out = (float*)d_out;

    const int E = in_sizes[1] / 2;
    const int* src = ei;
    const int* dst = ei + E;

    cudaFuncSetAttribute(k_layer, cudaFuncAttributeMaxDynamicSharedMemorySize, L_SMEM_BYTES);
    cudaFuncSetAttribute(k_gemm_in, cudaFuncAttributeMaxDynamicSharedMemorySize, GIN_BYTES);

    // CSR build (+ initial BN stat zero)
    k_zero_csr<<<(NN + 255) / 256, 256>>>();
    k_count<<<(E + 255) / 256, 256>>>(dst, E);
    k_scan<<<1, 1024>>>(E);
    k_fill<<<(E + 255) / 256, 256>>>(src, dst, E);

    // weight preprocessing (Wc + W_in merged)
    k_transAll<<<(3 * KTOT * HH + HH * HH) / 256, 256>>>(Wc, W_in);

    // input layer: h = relu(x @ W_in + b_in)  (3xBF16 MMA)
    k_gemm_in<<<NN / 128, 256, GIN_BYTES>>>(x, b_in);

    for (int l = 0; l < 3; l++) {
        k_layer<<<NN / 64, 128, L_SMEM_BYTES>>>(
            cen + l * RR * HH, wid + l * RR * HH, bc + l * RR * HH, l);
        k_aggregate<<<NN / 8, 256>>>();
        k_bn_stats<<<512, 128>>>(l & 1);
        k_bn_apply<<<1024, 256>>>(gamma + l * HH, beta + l * HH, l & 1);
    }

    k_head<<<NN, 128>>>(W_head, b_head, out);
}

// round 16
// speedup vs baseline: 1.1656x; 1.1656x over previous
#include <cuda_runtime.h>
#include <cuda_bf16.h>
#include <cstdint>

// ---------------- problem constants ----------------
constexpr int NN  = 32768;   // nodes
constexpr int HH  = 128;     // hidden
constexpr int RR  = 16;      // rules
constexpr int OUTC = 40;     // output classes
constexpr float EPS = 1e-5f;
constexpr int KTOT = RR * HH;   // 2048

// k_layer smem word offsets (frozen R7/R14 geometry)
constexpr int OFF_BC = 0;
constexpr int OFF_W  = 2048;
constexpr int OFF_A  = 4224;
constexpr int AW     = 68;
constexpr int A_TW   = 128 * AW;
constexpr int OFF_B  = OFF_A + 2 * A_TW;
constexpr int BW     = 36;
constexpr int B_TW   = 128 * BW;
constexpr int B_SW   = 2 * B_TW;
constexpr int SMEM_WORDS = OFF_B + 2 * B_SW;
constexpr int SMEM_BYTES = SMEM_WORDS * 4;

// k_gemm_in smem layout
constexpr int GW      = 68;
constexpr int G_TW    = 128 * GW;
constexpr int GIN_WORDS = 4 * G_TW;
constexpr int GIN_BYTES = GIN_WORDS * 4;

// ---------------- device scratch ----------------
__device__ __align__(16) float g_h[NN * HH];
__device__ __align__(16) float g_msg[NN * HH];
__device__ __align__(16) float g_a[NN * HH];
__device__ __align__(16) __nv_bfloat16 g_BtHi[3 * HH * KTOT];
__device__ __align__(16) __nv_bfloat16 g_BtLo[3 * HH * KTOT];
__device__ __align__(16) __nv_bfloat16 g_WinHi[HH * HH];
__device__ __align__(16) __nv_bfloat16 g_WinLo[HH * HH];
__device__ int   g_deg[NN];
__device__ int   g_cursor[NN];
__device__ int   g_rowptr[NN + 1];
__device__ int   g_col[1 << 20];
__device__ float g_sumS[2][HH];
__device__ float g_sumqS[2][HH];

// ---------------- helpers ----------------
__device__ __forceinline__ uint32_t smem_u32(const void* p) {
    uint32_t a;
    asm("{ .reg .u64 t; cvta.to.shared.u64 t, %1; cvt.u32.u64 %0, t; }" : "=r"(a) : "l"(p));
    return a;
}
__device__ __forceinline__ void cp_async16(uint32_t dst, const void* src) {
    asm volatile("cp.async.cg.shared.global [%0], [%1], 16;" :: "r"(dst), "l"(src));
}
__device__ __forceinline__ void cp_commit() {
    asm volatile("cp.async.commit_group;");
}
__device__ __forceinline__ void cp_wait0() {
    asm volatile("cp.async.wait_group 0;" ::: "memory");
}
__device__ __forceinline__ void sts_v2u(uint32_t addr, uint32_t a, uint32_t b) {
    asm volatile("st.shared.v2.b32 [%0], {%1, %2};" :: "r"(addr), "r"(a), "r"(b) : "memory");
}
__device__ __forceinline__ uint32_t pack_bf2(float a, float b) {
    __nv_bfloat162 t;
    t.x = __float2bfloat16(a);
    t.y = __float2bfloat16(b);
    return *(uint32_t*)&t;
}
__device__ __forceinline__ void mma_bf16(float* d, const uint32_t* a, const uint32_t* b) {
    asm volatile(
        "mma.sync.aligned.m16n8k16.row.col.f32.bf16.bf16.f32 "
        "{%0, %1, %2, %3}, {%4, %5, %6, %7}, {%8, %9}, {%0, %1, %2, %3};"
        : "+f"(d[0]), "+f"(d[1]), "+f"(d[2]), "+f"(d[3])
        : "r"(a[0]), "r"(a[1]), "r"(a[2]), "r"(a[3]), "r"(b[0]), "r"(b[1]));
}

// ---------------- CSR build (+ initial BN stat zero) ----------------
__global__ void k_zero_csr() {
    int i = blockIdx.x * blockDim.x + threadIdx.x;
    if (i < NN) { g_deg[i] = 0; g_cursor[i] = 0; }
    if (blockIdx.x == 0 && threadIdx.x < HH) {
        g_sumS[0][threadIdx.x] = 0.f; g_sumqS[0][threadIdx.x] = 0.f;
        g_sumS[1][threadIdx.x] = 0.f; g_sumqS[1][threadIdx.x] = 0.f;
    }
}

__global__ void k_count(const int* __restrict__ dst, int E) {
    int e = blockIdx.x * blockDim.x + threadIdx.x;
    if (e < E) atomicAdd(&g_deg[dst[e]], 1);
}

__global__ void k_scan(int E) {
    __shared__ int sh[1024];
    int t = threadIdx.x;
    int cnt[32];
    int tot = 0;
    #pragma unroll
    for (int i = 0; i < 32; i++) { cnt[i] = g_deg[t * 32 + i]; tot += cnt[i]; }
    sh[t] = tot;
    __syncthreads();
    for (int off = 1; off < 1024; off <<= 1) {
        int v = (t >= off) ? sh[t - off] : 0;
        __syncthreads();
        sh[t] += v;
        __syncthreads();
    }
    int base = sh[t] - tot;
    #pragma unroll
    for (int i = 0; i < 32; i++) { g_rowptr[t * 32 + i] = base; base += cnt[i]; }
    if (t == 1023) g_rowptr[NN] = E;
}

__global__ void k_fill(const int* __restrict__ src, const int* __restrict__ dst, int E) {
    int e = blockIdx.x * blockDim.x + threadIdx.x;
    if (e < E) {
        int d = dst[e];
        int p = atomicAdd(&g_cursor[d], 1);
        g_col[g_rowptr[d] + p] = src[e];
    }
}

// ---------------- combined weight preprocessing: Wc^T + W_in^T hi/lo splits ----------------
__global__ void k_transAll(const float* __restrict__ Wc, const float* __restrict__ Win) {
    int idx = blockIdx.x * blockDim.x + threadIdx.x;
    if (idx < 3 * KTOT * HH) {
        int l = idx >> 18;
        int rem = idx & 262143;
        int k = rem >> 7;
        int o = rem & 127;
        float v = Wc[idx];
        __nv_bfloat16 hi = __float2bfloat16(v);
        __nv_bfloat16 lo = __float2bfloat16(v - __bfloat162float(hi));
        size_t di = (size_t)l * 262144 + (size_t)o * KTOT + k;
        g_BtHi[di] = hi;
        g_BtLo[di] = lo;
    } else {
        int j = idx - 3 * KTOT * HH;
        int k = j >> 7;
        int o = j & 127;
        float v = Win[j];
        __nv_bfloat16 hi = __float2bfloat16(v);
        __nv_bfloat16 lo = __float2bfloat16(v - __bfloat162float(hi));
        g_WinHi[o * HH + k] = hi;
        g_WinLo[o * HH + k] = lo;
    }
}

// ---------------- input GEMM (3xBF16 MMA): g_h = relu(x @ W_in + b_in), K=128 ----------------
__global__ __launch_bounds__(256, 1) void k_gemm_in(
    const float* __restrict__ x, const float* __restrict__ bias)
{
    extern __shared__ float sm[];
    const uint32_t smBase = smem_u32(sm);
    uint32_t* SW = (uint32_t*)sm;

    const int tid  = threadIdx.x;
    const int m0   = blockIdx.x * 128;
    const int warp = tid >> 5, lane = tid & 31;
    const int mwarp = warp >> 2;
    const int nwarp = warp & 3;
    const int g   = lane >> 2;
    const int tig = lane & 3;

    #pragma unroll
    for (int i = 0; i < 16; i++) {
        int t = tid + i * 256;
        int row = t >> 5, seg = t & 31;
        float4 v = *(const float4*)&x[(size_t)(m0 + row) * HH + seg * 4];
        __nv_bfloat16 h0 = __float2bfloat16(v.x), h1 = __float2bfloat16(v.y);
        __nv_bfloat16 h2 = __float2bfloat16(v.z), h3 = __float2bfloat16(v.w);
        uint32_t hw0, hw1;
        { __nv_bfloat162 q; q.x = h0; q.y = h1; hw0 = *(uint32_t*)&q; }
        { __nv_bfloat162 q; q.x = h2; q.y = h3; hw1 = *(uint32_t*)&q; }
        uint32_t dst = smBase + (row * GW + seg * 2) * 4;
        sts_v2u(dst, hw0, hw1);
        uint32_t lw0 = pack_bf2(v.x - __bfloat162float(h0), v.y - __bfloat162float(h1));
        uint32_t lw1 = pack_bf2(v.z - __bfloat162float(h2), v.w - __bfloat162float(h3));
        sts_v2u(dst + G_TW * 4, lw0, lw1);
    }
    const uint4* bhp = (const uint4*)g_WinHi;
    const uint4* blp = (const uint4*)g_WinLo;
    #pragma unroll
    for (int i = 0; i < 8; i++) {
        int t = tid + i * 256;
        int row = t >> 4, seg = t & 15;
        uint4 vh = bhp[t];
        uint4 vl = blp[t];
        *(uint4*)((char*)sm + ((2 * G_TW + row * GW + seg * 4) * 4)) = vh;
        *(uint4*)((char*)sm + ((3 * G_TW + row * GW + seg * 4) * 4)) = vl;
    }
    __syncthreads();

    float acc[4][4][4];
    #pragma unroll
    for (int mi = 0; mi < 4; mi++)
        #pragma unroll
        for (int ni = 0; ni < 4; ni++)
            #pragma unroll
            for (int v = 0; v < 4; v++) acc[mi][ni][v] = 0.f;

    const uint32_t* Ah = SW;
    const uint32_t* Al = Ah + G_TW;
    const uint32_t* Bh = Ah + 2 * G_TW;
    const uint32_t* Bl = Ah + 3 * G_TW;

    #pragma unroll
    for (int ks = 0; ks < 8; ks++) {
        const int kw = ks * 8 + tig;
        uint32_t bh[4][2], bl[4][2];
        #pragma unroll
        for (int ni = 0; ni < 4; ni++) {
            int n = nwarp * 32 + ni * 8 + g;
            bh[ni][0] = Bh[n * GW + kw];
            bh[ni][1] = Bh[n * GW + kw + 4];
            bl[ni][0] = Bl[n * GW + kw];
            bl[ni][1] = Bl[n * GW + kw + 4];
        }
        #pragma unroll
        for (int mi = 0; mi < 4; mi++) {
            int m = mwarp * 64 + mi * 16;
            uint32_t ah[4], al[4];
            ah[0] = Ah[(m + g)     * GW + kw];
            ah[1] = Ah[(m + g + 8) * GW + kw];
            ah[2] = Ah[(m + g)     * GW + kw + 4];
            ah[3] = Ah[(m + g + 8) * GW + kw + 4];
            al[0] = Al[(m + g)     * GW + kw];
            al[1] = Al[(m + g + 8) * GW + kw];
            al[2] = Al[(m + g)     * GW + kw + 4];
            al[3] = Al[(m + g + 8) * GW + kw + 4];
            #pragma unroll
            for (int ni = 0; ni < 4; ni++) {
                mma_bf16(acc[mi][ni], ah, bh[ni]);
                mma_bf16(acc[mi][ni], al, bh[ni]);
                mma_bf16(acc[mi][ni], ah, bl[ni]);
            }
        }
    }

    #pragma unroll
    for (int mi = 0; mi < 4; mi++) {
        #pragma unroll
        for (int ni = 0; ni < 4; ni++) {
            int grow = m0 + mwarp * 64 + mi * 16 + g;
            int gcol = nwarp * 32 + ni * 8 + 2 * tig;
            float b0 = __ldg(&bias[gcol]);
            float b1 = __ldg(&bias[gcol + 1]);
            float2 v;
            v.x = fmaxf(acc[mi][ni][0] + b0, 0.f);
            v.y = fmaxf(acc[mi][ni][1] + b1, 0.f);
            *(float2*)&g_h[(size_t)grow * HH + gcol] = v;
            float2 u;
            u.x = fmaxf(acc[mi][ni][2] + b0, 0.f);
            u.y = fmaxf(acc[mi][ni][3] + b1, 0.f);
            *(float2*)&g_h[(size_t)(grow + 8) * HH + gcol] = u;
        }
    }
}

// ---------------- fused layer kernel (frozen R7/R14): rules + 3xBF16 rule-major GEMM ----------------
__global__ __launch_bounds__(256, 1) void k_layer(
    const float* __restrict__ cen, const float* __restrict__ wid,
    const float* __restrict__ bcl, int layer)
{
    extern __shared__ float sm[];
    const uint32_t smBase = smem_u32(sm);
    uint32_t* SW = (uint32_t*)sm;

    const __nv_bfloat16* __restrict__ BtHi = g_BtHi + (size_t)layer * (HH * KTOT);
    const __nv_bfloat16* __restrict__ BtLo = g_BtLo + (size_t)layer * (HH * KTOT);
    const int tid  = threadIdx.x;
    const int m0   = blockIdx.x * 128;
    const int warp = tid >> 5, lane = tid & 31;
    const int mwarp = warp >> 2;
    const int nwarp = warp & 3;
    const int g   = lane >> 2;
    const int tig = lane & 3;

    for (int i = tid; i < RR * HH; i += 256) {
        sm[OFF_BC + i] = bcl[i];
        sm[OFF_A + i] = cen[i];
        float w = wid[i];
        sm[OFF_A + 2048 + i] = 1.f / (2.f * w * w);
    }
    #pragma unroll
    for (int i = 0; i < 16; i++) {
        int t = tid + i * 256;
        int row = t >> 5, q = t & 31;
        *(float4*)&sm[OFF_B + row * 128 + q * 4] =
            *(const float4*)&g_h[(size_t)(m0 + row) * HH + q * 4];
    }
    __syncthreads();

    {
        const float* hraw = sm + OFF_B;
        const float* scen = sm + OFF_A;
        const float* ssiw = sm + OFF_A + 2048;
        for (int i = 0; i < 16; i++) {
            int node = warp * 16 + i;
            float4 h4 = *(const float4*)&hraw[node * 128 + lane * 4];
            float sr[16];
            #pragma unroll
            for (int r = 0; r < 16; r++) {
                float4 c  = *(const float4*)&scen[r * 128 + lane * 4];
                float4 iw = *(const float4*)&ssiw[r * 128 + lane * 4];
                float dx = h4.x - c.x, dy = h4.y - c.y, dz = h4.z - c.z, dw = h4.w - c.w;
                float p = dx * dx * iw.x + dy * dy * iw.y + dz * dz * iw.z + dw * dw * iw.w;
                #pragma unroll
                for (int o = 16; o; o >>= 1) p += __shfl_xor_sync(0xffffffffu, p, o);
                sr[r] = -p * (1.f / 128.f);
            }
            float m = sr[0];
            #pragma unroll
            for (int r = 1; r < 16; r++) m = fmaxf(m, sr[r]);
            float s = 0.f;
            #pragma unroll
            for (int r = 0; r < 16; r++) { sr[r] = expf(sr[r] - m); s += sr[r]; }
            float inv = 1.f / s;
            #pragma unroll
            for (int r = 0; r < 16; r++) {
                if (lane == r) sm[OFF_W + node * 17 + r] = sr[r] * inv;
            }
        }
    }
    __syncthreads();

    #pragma unroll
    for (int i = 0; i < 16; i++) {
        int t = tid + i * 256;
        int row = t >> 5, seg = t & 31;
        float4 v = *(const float4*)&sm[OFF_B + row * 128 + seg * 4];
        __nv_bfloat16 h0 = __float2bfloat16(v.x), h1 = __float2bfloat16(v.y);
        __nv_bfloat16 h2 = __float2bfloat16(v.z), h3 = __float2bfloat16(v.w);
        uint32_t hw0, hw1;
        { __nv_bfloat162 q; q.x = h0; q.y = h1; hw0 = *(uint32_t*)&q; }
        { __nv_bfloat162 q; q.x = h2; q.y = h3; hw1 = *(uint32_t*)&q; }
        uint32_t dst = smBase + (OFF_A + row * AW + seg * 2) * 4;
        sts_v2u(dst, hw0, hw1);
        uint32_t lw0 = pack_bf2(v.x - __bfloat162float(h0), v.y - __bfloat162float(h1));
        uint32_t lw1 = pack_bf2(v.z - __bfloat162float(h2), v.w - __bfloat162float(h3));
        sts_v2u(dst + A_TW * 4, lw0, lw1);
    }
    __syncthreads();

    float accT[4][4][4], accR[4][4][4];
    #pragma unroll
    for (int mi = 0; mi < 4; mi++)
        #pragma unroll
        for (int ni = 0; ni < 4; ni++)
            #pragma unroll
            for (int v = 0; v < 4; v++) { accT[mi][ni][v] = 0.f; accR[mi][ni][v] = 0.f; }

    auto cpB = [&](int c, int stage) {
        const int k0 = (c >> 1) * 128 + (c & 1) * 64;
        #pragma unroll
        for (int i = 0; i < 4; i++) {
            int t = tid + i * 256;
            int row = t >> 3, pc = t & 7;
            size_t gsrc = (size_t)row * KTOT + k0 + pc * 8;
            uint32_t dst = smBase + (OFF_B + stage * B_SW + row * BW + pc * 4) * 4;
            cp_async16(dst, &BtHi[gsrc]);
            cp_async16(dst + B_TW * 4, &BtLo[gsrc]);
        }
        cp_commit();
    };

    cpB(0, 0);

    for (int c = 0; c < 32; ++c) {
        const int s = c & 1;
        cp_wait0();
        __syncthreads();
        if (c + 1 < 32) cpB(c + 1, s ^ 1);

        const uint32_t* Ah = SW + OFF_A;
        const uint32_t* Al = Ah + A_TW;
        const uint32_t* Bh = SW + OFF_B + s * B_SW;
        const uint32_t* Bl = Bh + B_TW;
        const int abase = (c & 1) * 32;

        #pragma unroll
        for (int ks = 0; ks < 4; ks++) {
            const int kwB = ks * 8 + tig;
            const int kwA = abase + kwB;
            uint32_t bh[4][2], bl[4][2];
            #pragma unroll
            for (int ni = 0; ni < 4; ni++) {
                int n = nwarp * 32 + ni * 8 + g;
                bh[ni][0] = Bh[n * BW + kwB];
                bh[ni][1] = Bh[n * BW + kwB + 4];
                bl[ni][0] = Bl[n * BW + kwB];
                bl[ni][1] = Bl[n * BW + kwB + 4];
            }
            #pragma unroll
            for (int mi = 0; mi < 4; mi++) {
                int m = mwarp * 64 + mi * 16;
                uint32_t ah[4], al[4];
                ah[0] = Ah[(m + g)     * AW + kwA];
                ah[1] = Ah[(m + g + 8) * AW + kwA];
                ah[2] = Ah[(m + g)     * AW + kwA + 4];
                ah[3] = Ah[(m + g + 8) * AW + kwA + 4];
                al[0] = Al[(m + g)     * AW + kwA];
                al[1] = Al[(m + g + 8) * AW + kwA];
                al[2] = Al[(m + g)     * AW + kwA + 4];
                al[3] = Al[(m + g + 8) * AW + kwA + 4];
                #pragma unroll
                for (int ni = 0; ni < 4; ni++) {
                    mma_bf16(accR[mi][ni], ah, bh[ni]);
                    mma_bf16(accR[mi][ni], al, bh[ni]);
                    mma_bf16(accR[mi][ni], ah, bl[ni]);
                }
            }
        }

        if (c & 1) {
            const int r = c >> 1;
            #pragma unroll
            for (int mi = 0; mi < 4; mi++) {
                int mrow = mwarp * 64 + mi * 16 + g;
                float w0 = sm[OFF_W + mrow * 17 + r];
                float w1 = sm[OFF_W + (mrow + 8) * 17 + r];
                #pragma unroll
                for (int ni = 0; ni < 4; ni++) {
                    int col = nwarp * 32 + ni * 8 + 2 * tig;
                    float bc0 = sm[OFF_BC + r * 128 + col];
                    float bc1 = sm[OFF_BC + r * 128 + col + 1];
                    accT[mi][ni][0] += w0 * (accR[mi][ni][0] + bc0);
                    accT[mi][ni][1] += w0 * (accR[mi][ni][1] + bc1);
                    accT[mi][ni][2] += w1 * (accR[mi][ni][2] + bc0);
                    accT[mi][ni][3] += w1 * (accR[mi][ni][3] + bc1);
                    accR[mi][ni][0] = 0.f; accR[mi][ni][1] = 0.f;
                    accR[mi][ni][2] = 0.f; accR[mi][ni][3] = 0.f;
                }
            }
        }
    }

    #pragma unroll
    for (int mi = 0; mi < 4; mi++) {
        #pragma unroll
        for (int ni = 0; ni < 4; ni++) {
            int grow = m0 + mwarp * 64 + mi * 16 + g;
            int gcol = nwarp * 32 + ni * 8 + 2 * tig;
            float2 v; v.x = accT[mi][ni][0]; v.y = accT[mi][ni][1];
            *(float2*)&g_msg[(size_t)grow * HH + gcol] = v;
            float2 u; u.x = accT[mi][ni][2]; u.y = accT[mi][ni][3];
            *(float2*)&g_msg[(size_t)(grow + 8) * HH + gcol] = u;
        }
    }
}

// ---------------- edge aggregation (CSR gather, x4 unroll) + fused BN stats ----------------
// 4096 blocks, one node per warp (shape unchanged); block-reduce stats + 256 atomics/block.
__global__ __launch_bounds__(256) void k_aggregate(int parity) {
    __shared__ float ss[8][128];
    __shared__ float sq[8][128];
    const int tid = threadIdx.x, warp = tid >> 5, lane = tid & 31;
    const int n = blockIdx.x * 8 + warp;
    int s0 = g_rowptr[n], s1 = g_rowptr[n + 1];
    float4 acc0 = {0.f, 0.f, 0.f, 0.f};
    float4 acc1 = {0.f, 0.f, 0.f, 0.f};
    const float4* mp = (const float4*)g_msg;
    int j = s0;
    for (; j + 3 < s1; j += 4) {
        int i0 = g_col[j],     i1 = g_col[j + 1];
        int i2 = g_col[j + 2], i3 = g_col[j + 3];
        float4 v0 = mp[i0 * 32 + lane];
        float4 v1 = mp[i1 * 32 + lane];
        float4 v2 = mp[i2 * 32 + lane];
        float4 v3 = mp[i3 * 32 + lane];
        acc0.x += v0.x + v1.x; acc0.y += v0.y + v1.y;
        acc0.z += v0.z + v1.z; acc0.w += v0.w + v1.w;
        acc1.x += v2.x + v3.x; acc1.y += v2.y + v3.y;
        acc1.z += v2.z + v3.z; acc1.w += v2.w + v3.w;
    }
    for (; j < s1; j++) {
        int src = g_col[j];
        float4 v = mp[src * 32 + lane];
        acc0.x += v.x; acc0.y += v.y; acc0.z += v.z; acc0.w += v.w;
    }
    int d = s1 - s0;
    float invd = 1.f / (float)(d > 0 ? d : 1);
    float4 a;
    a.x = fmaxf((acc0.x + acc1.x) * invd, 0.f);
    a.y = fmaxf((acc0.y + acc1.y) * invd, 0.f);
    a.z = fmaxf((acc0.z + acc1.z) * invd, 0.f);
    a.w = fmaxf((acc0.w + acc1.w) * invd, 0.f);
    *(float4*)&g_a[(size_t)n * HH + lane * 4] = a;

    // fused BN stats: block-reduce then 2 atomics per feature
    ss[warp][lane * 4 + 0] = a.x; ss[warp][lane * 4 + 1] = a.y;
    ss[warp][lane * 4 + 2] = a.z; ss[warp][lane * 4 + 3] = a.w;
    sq[warp][lane * 4 + 0] = a.x * a.x; sq[warp][lane * 4 + 1] = a.y * a.y;
    sq[warp][lane * 4 + 2] = a.z * a.z; sq[warp][lane * 4 + 3] = a.w * a.w;
    __syncthreads();
    if (tid < 128) {
        float s = 0.f;
        #pragma unroll
        for (int w = 0; w < 8; w++) s += ss[w][tid];
        atomicAdd(&g_sumS[parity][tid], s);
    } else {
        int f = tid - 128;
        float s = 0.f;
        #pragma unroll
        for (int w = 0; w < 8; w++) s += sq[w][f];
        atomicAdd(&g_sumqS[parity][f], s);
    }
}

// ---------------- bn_apply: vectorized float4, zeroes next parity buffer ----------------
__global__ __launch_bounds__(256) void k_bn_apply(
    const float* __restrict__ gamma, const float* __restrict__ beta, int parity)
{
    __shared__ float smu[HH], ssc[HH], sbb[HH];
    const int tid = threadIdx.x;
    if (tid < 128) {
        const float inv_n = 1.f / (float)NN;
        float mu  = g_sumS[parity][tid] * inv_n;
        float var = g_sumqS[parity][tid] * inv_n - mu * mu;
        smu[tid] = mu;
        ssc[tid] = gamma[tid] * rsqrtf(var + EPS);
        sbb[tid] = beta[tid];
        if (blockIdx.x == 0) {
            g_sumS[parity ^ 1][tid] = 0.f;
            g_sumqS[parity ^ 1][tid] = 0.f;
        }
    }
    __syncthreads();
    const int lane = tid & 31;
    const int wrp  = tid >> 5;
    const int f = lane * 4;
    float4 mu4 = *(float4*)&smu[f];
    float4 sc4 = *(float4*)&ssc[f];
    float4 bb4 = *(float4*)&sbb[f];
    for (int row = blockIdx.x * 8 + wrp; row < NN; row += gridDim.x * 8) {
        size_t gi = (size_t)row * HH + f;
        float4 h4 = *(float4*)&g_h[gi];
        float4 a4 = *(const float4*)&g_a[gi];
        h4.x += (a4.x - mu4.x) * sc4.x + bb4.x;
        h4.y += (a4.y - mu4.y) * sc4.y + bb4.y;
        h4.z += (a4.z - mu4.z) * sc4.z + bb4.z;
        h4.w += (a4.w - mu4.w) * sc4.w + bb4.w;
        *(float4*)&g_h[gi] = h4;
    }
}

// ---------------- head: out = softmax(h @ W_head + b_head) ----------------
__global__ __launch_bounds__(128) void k_head(
    const float* __restrict__ W, const float* __restrict__ b, float* __restrict__ out)
{
    __shared__ float hs[HH];
    __shared__ float lg[OUTC];
    __shared__ float red[2];
    const int t = threadIdx.x;
    const int n = blockIdx.x;
    hs[t] = g_h[n * HH + t];
    __syncthreads();
    if (t < OUTC) {
        float acc = b[t];
        #pragma unroll 8
        for (int k = 0; k < HH; k++) acc += hs[k] * W[k * OUTC + t];
        lg[t] = acc;
    }
    __syncthreads();
    if (t == 0) {
        float m = lg[0];
        for (int i = 1; i < OUTC; i++) m = fmaxf(m, lg[i]);
        red[0] = m;
    }
    __syncthreads();
    if (t < OUTC) lg[t] = expf(lg[t] - red[0]);
    __syncthreads();
    if (t == 0) {
        float s = 0.f;
        for (int i = 0; i < OUTC; i++) s += lg[i];
        red[1] = 1.f / s;
    }
    __syncthreads();
    if (t < OUTC) out[n * OUTC + t] = lg[t] * red[1];
}

// ---------------- launch ----------------
extern "C" void kernel_launch(void* const* d_in, const int* in_sizes, int n_in,
                              void* d_out, int out_size)
{
    const float* x      = (const float*)d_in[0];
    const int*   ei     = (const int*)d_in[1];
    const float* W_in   = (const float*)d_in[2];
    const float* b_in   = (const float*)d_in[3];
    const float* cen    = (const float*)d_in[4];
    const float* wid    = (const float*)d_in[5];
    const float* Wc     = (const float*)d_in[6];
    const float* bc     = (const float*)d_in[7];
    const float* gamma  = (const float*)d_in[8];
    const float* beta   = (const float*)d_in[9];
    const float* W_head = (const float*)d_in[10];
    const float* b_head = (const float*)d_in[11];
    float* out = (float*)d_out;

    const int E = in_sizes[1] / 2;
    const int* src = ei;
    const int* dst = ei + E;

    cudaFuncSetAttribute(k_layer, cudaFuncAttributeMaxDynamicSharedMemorySize, SMEM_BYTES);
    cudaFuncSetAttribute(k_gemm_in, cudaFuncAttributeMaxDynamicSharedMemorySize, GIN_BYTES);

    // CSR build (+ initial BN stat zero)
    k_zero_csr<<<(NN + 255) / 256, 256>>>();
    k_count<<<(E + 255) / 256, 256>>>(dst, E);
    k_scan<<<1, 1024>>>(E);
    k_fill<<<(E + 255) / 256, 256>>>(src, dst, E);

    // weight preprocessing (Wc + W_in merged)
    k_transAll<<<(3 * KTOT * HH + HH * HH) / 256, 256>>>(Wc, W_in);

    // input layer: h = relu(x @ W_in + b_in)  (3xBF16 MMA)
    k_gemm_in<<<NN / 128, 256, GIN_BYTES>>>(x, b_in);

    for (int l = 0; l < 3; l++) {
        k_layer<<<NN / 128, 256, SMEM_BYTES>>>(
            cen + l * RR * HH, wid + l * RR * HH, bc + l * RR * HH, l);
        k_aggregate<<<NN / 8, 256>>>(l & 1);
        k_bn_apply<<<1024, 256>>>(gamma + l * HH, beta + l * HH, l & 1);
    }

    k_head<<<NN, 128>>>(W_head, b_head, out);
}

// round 17
// speedup vs baseline: 1.1821x; 1.0142x over previous
#include <cuda_runtime.h>
#include <cuda_bf16.h>
#include <cstdint>

// ---------------- problem constants ----------------
constexpr int NN  = 32768;   // nodes
constexpr int HH  = 128;     // hidden
constexpr int RR  = 16;      // rules
constexpr int OUTC = 40;     // output classes
constexpr float EPS = 1e-5f;
constexpr int KTOT = RR * HH;   // 2048

// k_layer smem word offsets (frozen R7/R14 geometry)
constexpr int OFF_BC = 0;
constexpr int OFF_W  = 2048;
constexpr int OFF_A  = 4224;
constexpr int AW     = 68;
constexpr int A_TW   = 128 * AW;
constexpr int OFF_B  = OFF_A + 2 * A_TW;
constexpr int BW     = 36;
constexpr int B_TW   = 128 * BW;
constexpr int B_SW   = 2 * B_TW;
constexpr int SMEM_WORDS = OFF_B + 2 * B_SW;
constexpr int SMEM_BYTES = SMEM_WORDS * 4;

// k_gemm_in smem layout
constexpr int GW      = 68;
constexpr int G_TW    = 128 * GW;
constexpr int GIN_WORDS = 4 * G_TW;
constexpr int GIN_BYTES = GIN_WORDS * 4;

// k_head smem word offsets (dynamic)
constexpr int H_W  = 0;                  // W: 128*40 = 5120 w
constexpr int H_H  = 5120;               // h tile: 64*128 = 8192 w
constexpr int H_L  = H_H + 8192;         // logits: 64*40 = 2560 w
constexpr int H_B  = H_L + 2560;         // bias: 40 w
constexpr int HEAD_WORDS = H_B + 40;     // 15912
constexpr int HEAD_BYTES = HEAD_WORDS * 4;  // 63648

// ---------------- device scratch ----------------
__device__ __align__(16) float g_h[NN * HH];
__device__ __align__(16) float g_msg[NN * HH];
__device__ __align__(16) float g_a[NN * HH];
__device__ __align__(16) __nv_bfloat16 g_BtHi[3 * HH * KTOT];
__device__ __align__(16) __nv_bfloat16 g_BtLo[3 * HH * KTOT];
__device__ __align__(16) __nv_bfloat16 g_WinHi[HH * HH];
__device__ __align__(16) __nv_bfloat16 g_WinLo[HH * HH];
__device__ int   g_deg[NN];
__device__ int   g_cursor[NN];
__device__ int   g_rowptr[NN + 1];
__device__ int   g_col[1 << 20];
__device__ float g_sumS[2][HH];
__device__ float g_sumqS[2][HH];

// ---------------- helpers ----------------
__device__ __forceinline__ uint32_t smem_u32(const void* p) {
    uint32_t a;
    asm("{ .reg .u64 t; cvta.to.shared.u64 t, %1; cvt.u32.u64 %0, t; }" : "=r"(a) : "l"(p));
    return a;
}
__device__ __forceinline__ void cp_async16(uint32_t dst, const void* src) {
    asm volatile("cp.async.cg.shared.global [%0], [%1], 16;" :: "r"(dst), "l"(src));
}
__device__ __forceinline__ void cp_commit() {
    asm volatile("cp.async.commit_group;");
}
__device__ __forceinline__ void cp_wait0() {
    asm volatile("cp.async.wait_group 0;" ::: "memory");
}
__device__ __forceinline__ void sts_v2u(uint32_t addr, uint32_t a, uint32_t b) {
    asm volatile("st.shared.v2.b32 [%0], {%1, %2};" :: "r"(addr), "r"(a), "r"(b) : "memory");
}
__device__ __forceinline__ uint32_t pack_bf2(float a, float b) {
    __nv_bfloat162 t;
    t.x = __float2bfloat16(a);
    t.y = __float2bfloat16(b);
    return *(uint32_t*)&t;
}
__device__ __forceinline__ void mma_bf16(float* d, const uint32_t* a, const uint32_t* b) {
    asm volatile(
        "mma.sync.aligned.m16n8k16.row.col.f32.bf16.bf16.f32 "
        "{%0, %1, %2, %3}, {%4, %5, %6, %7}, {%8, %9}, {%0, %1, %2, %3};"
        : "+f"(d[0]), "+f"(d[1]), "+f"(d[2]), "+f"(d[3])
        : "r"(a[0]), "r"(a[1]), "r"(a[2]), "r"(a[3]), "r"(b[0]), "r"(b[1]));
}

// ---------------- CSR build (+ initial BN stat zero) ----------------
__global__ void k_zero_csr() {
    int i = blockIdx.x * blockDim.x + threadIdx.x;
    if (i < NN) { g_deg[i] = 0; g_cursor[i] = 0; }
    if (blockIdx.x == 0 && threadIdx.x < HH) {
        g_sumS[0][threadIdx.x] = 0.f; g_sumqS[0][threadIdx.x] = 0.f;
        g_sumS[1][threadIdx.x] = 0.f; g_sumqS[1][threadIdx.x] = 0.f;
    }
}

__global__ void k_count(const int* __restrict__ dst, int E) {
    int e = blockIdx.x * blockDim.x + threadIdx.x;
    if (e < E) atomicAdd(&g_deg[dst[e]], 1);
}

__global__ void k_scan(int E) {
    __shared__ int sh[1024];
    int t = threadIdx.x;
    int cnt[32];
    int tot = 0;
    #pragma unroll
    for (int i = 0; i < 32; i++) { cnt[i] = g_deg[t * 32 + i]; tot += cnt[i]; }
    sh[t] = tot;
    __syncthreads();
    for (int off = 1; off < 1024; off <<= 1) {
        int v = (t >= off) ? sh[t - off] : 0;
        __syncthreads();
        sh[t] += v;
        __syncthreads();
    }
    int base = sh[t] - tot;
    #pragma unroll
    for (int i = 0; i < 32; i++) { g_rowptr[t * 32 + i] = base; base += cnt[i]; }
    if (t == 1023) g_rowptr[NN] = E;
}

__global__ void k_fill(const int* __restrict__ src, const int* __restrict__ dst, int E) {
    int e = blockIdx.x * blockDim.x + threadIdx.x;
    if (e < E) {
        int d = dst[e];
        int p = atomicAdd(&g_cursor[d], 1);
        g_col[g_rowptr[d] + p] = src[e];
    }
}

// ---------------- combined weight preprocessing: Wc^T + W_in^T hi/lo splits ----------------
__global__ void k_transAll(const float* __restrict__ Wc, const float* __restrict__ Win) {
    int idx = blockIdx.x * blockDim.x + threadIdx.x;
    if (idx < 3 * KTOT * HH) {
        int l = idx >> 18;
        int rem = idx & 262143;
        int k = rem >> 7;
        int o = rem & 127;
        float v = Wc[idx];
        __nv_bfloat16 hi = __float2bfloat16(v);
        __nv_bfloat16 lo = __float2bfloat16(v - __bfloat162float(hi));
        size_t di = (size_t)l * 262144 + (size_t)o * KTOT + k;
        g_BtHi[di] = hi;
        g_BtLo[di] = lo;
    } else {
        int j = idx - 3 * KTOT * HH;
        int k = j >> 7;
        int o = j & 127;
        float v = Win[j];
        __nv_bfloat16 hi = __float2bfloat16(v);
        __nv_bfloat16 lo = __float2bfloat16(v - __bfloat162float(hi));
        g_WinHi[o * HH + k] = hi;
        g_WinLo[o * HH + k] = lo;
    }
}

// ---------------- input GEMM (3xBF16 MMA): g_h = relu(x @ W_in + b_in), K=128 ----------------
__global__ __launch_bounds__(256, 1) void k_gemm_in(
    const float* __restrict__ x, const float* __restrict__ bias)
{
    extern __shared__ float sm[];
    const uint32_t smBase = smem_u32(sm);
    uint32_t* SW = (uint32_t*)sm;

    const int tid  = threadIdx.x;
    const int m0   = blockIdx.x * 128;
    const int warp = tid >> 5, lane = tid & 31;
    const int mwarp = warp >> 2;
    const int nwarp = warp & 3;
    const int g   = lane >> 2;
    const int tig = lane & 3;

    #pragma unroll
    for (int i = 0; i < 16; i++) {
        int t = tid + i * 256;
        int row = t >> 5, seg = t & 31;
        float4 v = *(const float4*)&x[(size_t)(m0 + row) * HH + seg * 4];
        __nv_bfloat16 h0 = __float2bfloat16(v.x), h1 = __float2bfloat16(v.y);
        __nv_bfloat16 h2 = __float2bfloat16(v.z), h3 = __float2bfloat16(v.w);
        uint32_t hw0, hw1;
        { __nv_bfloat162 q; q.x = h0; q.y = h1; hw0 = *(uint32_t*)&q; }
        { __nv_bfloat162 q; q.x = h2; q.y = h3; hw1 = *(uint32_t*)&q; }
        uint32_t dst = smBase + (row * GW + seg * 2) * 4;
        sts_v2u(dst, hw0, hw1);
        uint32_t lw0 = pack_bf2(v.x - __bfloat162float(h0), v.y - __bfloat162float(h1));
        uint32_t lw1 = pack_bf2(v.z - __bfloat162float(h2), v.w - __bfloat162float(h3));
        sts_v2u(dst + G_TW * 4, lw0, lw1);
    }
    const uint4* bhp = (const uint4*)g_WinHi;
    const uint4* blp = (const uint4*)g_WinLo;
    #pragma unroll
    for (int i = 0; i < 8; i++) {
        int t = tid + i * 256;
        int row = t >> 4, seg = t & 15;
        uint4 vh = bhp[t];
        uint4 vl = blp[t];
        *(uint4*)((char*)sm + ((2 * G_TW + row * GW + seg * 4) * 4)) = vh;
        *(uint4*)((char*)sm + ((3 * G_TW + row * GW + seg * 4) * 4)) = vl;
    }
    __syncthreads();

    float acc[4][4][4];
    #pragma unroll
    for (int mi = 0; mi < 4; mi++)
        #pragma unroll
        for (int ni = 0; ni < 4; ni++)
            #pragma unroll
            for (int v = 0; v < 4; v++) acc[mi][ni][v] = 0.f;

    const uint32_t* Ah = SW;
    const uint32_t* Al = Ah + G_TW;
    const uint32_t* Bh = Ah + 2 * G_TW;
    const uint32_t* Bl = Ah + 3 * G_TW;

    #pragma unroll
    for (int ks = 0; ks < 8; ks++) {
        const int kw = ks * 8 + tig;
        uint32_t bh[4][2], bl[4][2];
        #pragma unroll
        for (int ni = 0; ni < 4; ni++) {
            int n = nwarp * 32 + ni * 8 + g;
            bh[ni][0] = Bh[n * GW + kw];
            bh[ni][1] = Bh[n * GW + kw + 4];
            bl[ni][0] = Bl[n * GW + kw];
            bl[ni][1] = Bl[n * GW + kw + 4];
        }
        #pragma unroll
        for (int mi = 0; mi < 4; mi++) {
            int m = mwarp * 64 + mi * 16;
            uint32_t ah[4], al[4];
            ah[0] = Ah[(m + g)     * GW + kw];
            ah[1] = Ah[(m + g + 8) * GW + kw];
            ah[2] = Ah[(m + g)     * GW + kw + 4];
            ah[3] = Ah[(m + g + 8) * GW + kw + 4];
            al[0] = Al[(m + g)     * GW + kw];
            al[1] = Al[(m + g + 8) * GW + kw];
            al[2] = Al[(m + g)     * GW + kw + 4];
            al[3] = Al[(m + g + 8) * GW + kw + 4];
            #pragma unroll
            for (int ni = 0; ni < 4; ni++) {
                mma_bf16(acc[mi][ni], ah, bh[ni]);
                mma_bf16(acc[mi][ni], al, bh[ni]);
                mma_bf16(acc[mi][ni], ah, bl[ni]);
            }
        }
    }

    #pragma unroll
    for (int mi = 0; mi < 4; mi++) {
        #pragma unroll
        for (int ni = 0; ni < 4; ni++) {
            int grow = m0 + mwarp * 64 + mi * 16 + g;
            int gcol = nwarp * 32 + ni * 8 + 2 * tig;
            float b0 = __ldg(&bias[gcol]);
            float b1 = __ldg(&bias[gcol + 1]);
            float2 v;
            v.x = fmaxf(acc[mi][ni][0] + b0, 0.f);
            v.y = fmaxf(acc[mi][ni][1] + b1, 0.f);
            *(float2*)&g_h[(size_t)grow * HH + gcol] = v;
            float2 u;
            u.x = fmaxf(acc[mi][ni][2] + b0, 0.f);
            u.y = fmaxf(acc[mi][ni][3] + b1, 0.f);
            *(float2*)&g_h[(size_t)(grow + 8) * HH + gcol] = u;
        }
    }
}

// ---------------- fused layer kernel (frozen R7/R14): rules + 3xBF16 rule-major GEMM ----------------
__global__ __launch_bounds__(256, 1) void k_layer(
    const float* __restrict__ cen, const float* __restrict__ wid,
    const float* __restrict__ bcl, int layer)
{
    extern __shared__ float sm[];
    const uint32_t smBase = smem_u32(sm);
    uint32_t* SW = (uint32_t*)sm;

    const __nv_bfloat16* __restrict__ BtHi = g_BtHi + (size_t)layer * (HH * KTOT);
    const __nv_bfloat16* __restrict__ BtLo = g_BtLo + (size_t)layer * (HH * KTOT);
    const int tid  = threadIdx.x;
    const int m0   = blockIdx.x * 128;
    const int warp = tid >> 5, lane = tid & 31;
    const int mwarp = warp >> 2;
    const int nwarp = warp & 3;
    const int g   = lane >> 2;
    const int tig = lane & 3;

    for (int i = tid; i < RR * HH; i += 256) {
        sm[OFF_BC + i] = bcl[i];
        sm[OFF_A + i] = cen[i];
        float w = wid[i];
        sm[OFF_A + 2048 + i] = 1.f / (2.f * w * w);
    }
    #pragma unroll
    for (int i = 0; i < 16; i++) {
        int t = tid + i * 256;
        int row = t >> 5, q = t & 31;
        *(float4*)&sm[OFF_B + row * 128 + q * 4] =
            *(const float4*)&g_h[(size_t)(m0 + row) * HH + q * 4];
    }
    __syncthreads();

    {
        const float* hraw = sm + OFF_B;
        const float* scen = sm + OFF_A;
        const float* ssiw = sm + OFF_A + 2048;
        for (int i = 0; i < 16; i++) {
            int node = warp * 16 + i;
            float4 h4 = *(const float4*)&hraw[node * 128 + lane * 4];
            float sr[16];
            #pragma unroll
            for (int r = 0; r < 16; r++) {
                float4 c  = *(const float4*)&scen[r * 128 + lane * 4];
                float4 iw = *(const float4*)&ssiw[r * 128 + lane * 4];
                float dx = h4.x - c.x, dy = h4.y - c.y, dz = h4.z - c.z, dw = h4.w - c.w;
                float p = dx * dx * iw.x + dy * dy * iw.y + dz * dz * iw.z + dw * dw * iw.w;
                #pragma unroll
                for (int o = 16; o; o >>= 1) p += __shfl_xor_sync(0xffffffffu, p, o);
                sr[r] = -p * (1.f / 128.f);
            }
            float m = sr[0];
            #pragma unroll
            for (int r = 1; r < 16; r++) m = fmaxf(m, sr[r]);
            float s = 0.f;
            #pragma unroll
            for (int r = 0; r < 16; r++) { sr[r] = expf(sr[r] - m); s += sr[r]; }
            float inv = 1.f / s;
            #pragma unroll
            for (int r = 0; r < 16; r++) {
                if (lane == r) sm[OFF_W + node * 17 + r] = sr[r] * inv;
            }
        }
    }
    __syncthreads();

    #pragma unroll
    for (int i = 0; i < 16; i++) {
        int t = tid + i * 256;
        int row = t >> 5, seg = t & 31;
        float4 v = *(const float4*)&sm[OFF_B + row * 128 + seg * 4];
        __nv_bfloat16 h0 = __float2bfloat16(v.x), h1 = __float2bfloat16(v.y);
        __nv_bfloat16 h2 = __float2bfloat16(v.z), h3 = __float2bfloat16(v.w);
        uint32_t hw0, hw1;
        { __nv_bfloat162 q; q.x = h0; q.y = h1; hw0 = *(uint32_t*)&q; }
        { __nv_bfloat162 q; q.x = h2; q.y = h3; hw1 = *(uint32_t*)&q; }
        uint32_t dst = smBase + (OFF_A + row * AW + seg * 2) * 4;
        sts_v2u(dst, hw0, hw1);
        uint32_t lw0 = pack_bf2(v.x - __bfloat162float(h0), v.y - __bfloat162float(h1));
        uint32_t lw1 = pack_bf2(v.z - __bfloat162float(h2), v.w - __bfloat162float(h3));
        sts_v2u(dst + A_TW * 4, lw0, lw1);
    }
    __syncthreads();

    float accT[4][4][4], accR[4][4][4];
    #pragma unroll
    for (int mi = 0; mi < 4; mi++)
        #pragma unroll
        for (int ni = 0; ni < 4; ni++)
            #pragma unroll
            for (int v = 0; v < 4; v++) { accT[mi][ni][v] = 0.f; accR[mi][ni][v] = 0.f; }

    auto cpB = [&](int c, int stage) {
        const int k0 = (c >> 1) * 128 + (c & 1) * 64;
        #pragma unroll
        for (int i = 0; i < 4; i++) {
            int t = tid + i * 256;
            int row = t >> 3, pc = t & 7;
            size_t gsrc = (size_t)row * KTOT + k0 + pc * 8;
            uint32_t dst = smBase + (OFF_B + stage * B_SW + row * BW + pc * 4) * 4;
            cp_async16(dst, &BtHi[gsrc]);
            cp_async16(dst + B_TW * 4, &BtLo[gsrc]);
        }
        cp_commit();
    };

    cpB(0, 0);

    for (int c = 0; c < 32; ++c) {
        const int s = c & 1;
        cp_wait0();
        __syncthreads();
        if (c + 1 < 32) cpB(c + 1, s ^ 1);

        const uint32_t* Ah = SW + OFF_A;
        const uint32_t* Al = Ah + A_TW;
        const uint32_t* Bh = SW + OFF_B + s * B_SW;
        const uint32_t* Bl = Bh + B_TW;
        const int abase = (c & 1) * 32;

        #pragma unroll
        for (int ks = 0; ks < 4; ks++) {
            const int kwB = ks * 8 + tig;
            const int kwA = abase + kwB;
            uint32_t bh[4][2], bl[4][2];
            #pragma unroll
            for (int ni = 0; ni < 4; ni++) {
                int n = nwarp * 32 + ni * 8 + g;
                bh[ni][0] = Bh[n * BW + kwB];
                bh[ni][1] = Bh[n * BW + kwB + 4];
                bl[ni][0] = Bl[n * BW + kwB];
                bl[ni][1] = Bl[n * BW + kwB + 4];
            }
            #pragma unroll
            for (int mi = 0; mi < 4; mi++) {
                int m = mwarp * 64 + mi * 16;
                uint32_t ah[4], al[4];
                ah[0] = Ah[(m + g)     * AW + kwA];
                ah[1] = Ah[(m + g + 8) * AW + kwA];
                ah[2] = Ah[(m + g)     * AW + kwA + 4];
                ah[3] = Ah[(m + g + 8) * AW + kwA + 4];
                al[0] = Al[(m + g)     * AW + kwA];
                al[1] = Al[(m + g + 8) * AW + kwA];
                al[2] = Al[(m + g)     * AW + kwA + 4];
                al[3] = Al[(m + g + 8) * AW + kwA + 4];
                #pragma unroll
                for (int ni = 0; ni < 4; ni++) {
                    mma_bf16(accR[mi][ni], ah, bh[ni]);
                    mma_bf16(accR[mi][ni], al, bh[ni]);
                    mma_bf16(accR[mi][ni], ah, bl[ni]);
                }
            }
        }

        if (c & 1) {
            const int r = c >> 1;
            #pragma unroll
            for (int mi = 0; mi < 4; mi++) {
                int mrow = mwarp * 64 + mi * 16 + g;
                float w0 = sm[OFF_W + mrow * 17 + r];
                float w1 = sm[OFF_W + (mrow + 8) * 17 + r];
                #pragma unroll
                for (int ni = 0; ni < 4; ni++) {
                    int col = nwarp * 32 + ni * 8 + 2 * tig;
                    float bc0 = sm[OFF_BC + r * 128 + col];
                    float bc1 = sm[OFF_BC + r * 128 + col + 1];
                    accT[mi][ni][0] += w0 * (accR[mi][ni][0] + bc0);
                    accT[mi][ni][1] += w0 * (accR[mi][ni][1] + bc1);
                    accT[mi][ni][2] += w1 * (accR[mi][ni][2] + bc0);
                    accT[mi][ni][3] += w1 * (accR[mi][ni][3] + bc1);
                    accR[mi][ni][0] = 0.f; accR[mi][ni][1] = 0.f;
                    accR[mi][ni][2] = 0.f; accR[mi][ni][3] = 0.f;
                }
            }
        }
    }

    #pragma unroll
    for (int mi = 0; mi < 4; mi++) {
        #pragma unroll
        for (int ni = 0; ni < 4; ni++) {
            int grow = m0 + mwarp * 64 + mi * 16 + g;
            int gcol = nwarp * 32 + ni * 8 + 2 * tig;
            float2 v; v.x = accT[mi][ni][0]; v.y = accT[mi][ni][1];
            *(float2*)&g_msg[(size_t)grow * HH + gcol] = v;
            float2 u; u.x = accT[mi][ni][2]; u.y = accT[mi][ni][3];
            *(float2*)&g_msg[(size_t)(grow + 8) * HH + gcol] = u;
        }
    }
}

// ---------------- edge aggregation (CSR gather, x4 unroll) + fused BN stats ----------------
__global__ __launch_bounds__(256) void k_aggregate(int parity) {
    __shared__ float ss[8][128];
    __shared__ float sq[8][128];
    const int tid = threadIdx.x, warp = tid >> 5, lane = tid & 31;
    const int n = blockIdx.x * 8 + warp;
    int s0 = g_rowptr[n], s1 = g_rowptr[n + 1];
    float4 acc0 = {0.f, 0.f, 0.f, 0.f};
    float4 acc1 = {0.f, 0.f, 0.f, 0.f};
    const float4* mp = (const float4*)g_msg;
    int j = s0;
    for (; j + 3 < s1; j += 4) {
        int i0 = g_col[j],     i1 = g_col[j + 1];
        int i2 = g_col[j + 2], i3 = g_col[j + 3];
        float4 v0 = mp[i0 * 32 + lane];
        float4 v1 = mp[i1 * 32 + lane];
        float4 v2 = mp[i2 * 32 + lane];
        float4 v3 = mp[i3 * 32 + lane];
        acc0.x += v0.x + v1.x; acc0.y += v0.y + v1.y;
        acc0.z += v0.z + v1.z; acc0.w += v0.w + v1.w;
        acc1.x += v2.x + v3.x; acc1.y += v2.y + v3.y;
        acc1.z += v2.z + v3.z; acc1.w += v2.w + v3.w;
    }
    for (; j < s1; j++) {
        int src = g_col[j];
        float4 v = mp[src * 32 + lane];
        acc0.x += v.x; acc0.y += v.y; acc0.z += v.z; acc0.w += v.w;
    }
    int d = s1 - s0;
    float invd = 1.f / (float)(d > 0 ? d : 1);
    float4 a;
    a.x = fmaxf((acc0.x + acc1.x) * invd, 0.f);
    a.y = fmaxf((acc0.y + acc1.y) * invd, 0.f);
    a.z = fmaxf((acc0.z + acc1.z) * invd, 0.f);
    a.w = fmaxf((acc0.w + acc1.w) * invd, 0.f);
    *(float4*)&g_a[(size_t)n * HH + lane * 4] = a;

    ss[warp][lane * 4 + 0] = a.x; ss[warp][lane * 4 + 1] = a.y;
    ss[warp][lane * 4 + 2] = a.z; ss[warp][lane * 4 + 3] = a.w;
    sq[warp][lane * 4 + 0] = a.x * a.x; sq[warp][lane * 4 + 1] = a.y * a.y;
    sq[warp][lane * 4 + 2] = a.z * a.z; sq[warp][lane * 4 + 3] = a.w * a.w;
    __syncthreads();
    if (tid < 128) {
        float s = 0.f;
        #pragma unroll
        for (int w = 0; w < 8; w++) s += ss[w][tid];
        atomicAdd(&g_sumS[parity][tid], s);
    } else {
        int f = tid - 128;
        float s = 0.f;
        #pragma unroll
        for (int w = 0; w < 8; w++) s += sq[w][f];
        atomicAdd(&g_sumqS[parity][f], s);
    }
}

// ---------------- bn_apply: vectorized float4, zeroes next parity buffer ----------------
__global__ __launch_bounds__(256) void k_bn_apply(
    const float* __restrict__ gamma, const float* __restrict__ beta, int parity)
{
    __shared__ float smu[HH], ssc[HH], sbb[HH];
    const int tid = threadIdx.x;
    if (tid < 128) {
        const float inv_n = 1.f / (float)NN;
        float mu  = g_sumS[parity][tid] * inv_n;
        float var = g_sumqS[parity][tid] * inv_n - mu * mu;
        smu[tid] = mu;
        ssc[tid] = gamma[tid] * rsqrtf(var + EPS);
        sbb[tid] = beta[tid];
        if (blockIdx.x == 0) {
            g_sumS[parity ^ 1][tid] = 0.f;
            g_sumqS[parity ^ 1][tid] = 0.f;
        }
    }
    __syncthreads();
    const int lane = tid & 31;
    const int wrp  = tid >> 5;
    const int f = lane * 4;
    float4 mu4 = *(float4*)&smu[f];
    float4 sc4 = *(float4*)&ssc[f];
    float4 bb4 = *(float4*)&sbb[f];
    for (int row = blockIdx.x * 8 + wrp; row < NN; row += gridDim.x * 8) {
        size_t gi = (size_t)row * HH + f;
        float4 h4 = *(float4*)&g_h[gi];
        float4 a4 = *(const float4*)&g_a[gi];
        h4.x += (a4.x - mu4.x) * sc4.x + bb4.x;
        h4.y += (a4.y - mu4.y) * sc4.y + bb4.y;
        h4.z += (a4.z - mu4.z) * sc4.z + bb4.z;
        h4.w += (a4.w - mu4.w) * sc4.w + bb4.w;
        *(float4*)&g_h[gi] = h4;
    }
}

// ---------------- head: out = softmax(h @ W_head + b_head) ----------------
// 512 blocks x 64 nodes; W + h tile + logits in dynamic smem; FMA-based dot products.
// thread: node = tid>>2, osub = tid&3, computes 10 logits o = osub + 4*i.
__global__ __launch_bounds__(256) void k_head(
    const float* __restrict__ W, const float* __restrict__ b, float* __restrict__ out)
{
    extern __shared__ float sm[];
    const int tid = threadIdx.x;
    const int m0 = blockIdx.x * 64;

    // load W [128][40] (no transpose) and bias
    for (int i = tid; i < HH * OUTC; i += 256) sm[H_W + i] = W[i];
    if (tid < OUTC) sm[H_B + tid] = b[tid];
    // load h tile 64 x 128 (float4)
    #pragma unroll
    for (int i = 0; i < 8; i++) {
        int t = tid + i * 256;          // 0..2047 float4 units
        int row = t >> 5, q = t & 31;
        *(float4*)&sm[H_H + row * 128 + q * 4] =
            *(const float4*)&g_h[(size_t)(m0 + row) * HH + q * 4];
    }
    __syncthreads();

    // logits: register-accumulated FMA loops
    {
        const int node = tid >> 2;
        const int osub = tid & 3;
        const float* hrow = sm + H_H + node * 128;
        float acc[10];
        #pragma unroll
        for (int i = 0; i < 10; i++) acc[i] = sm[H_B + osub + 4 * i];
        #pragma unroll 4
        for (int k = 0; k < 128; k++) {
            float hk = hrow[k];
            const float* wrow = sm + H_W + k * OUTC + osub;
            #pragma unroll
            for (int i = 0; i < 10; i++) acc[i] += hk * wrow[4 * i];
        }
        #pragma unroll
        for (int i = 0; i < 10; i++) sm[H_L + node * OUTC + osub + 4 * i] = acc[i];
    }
    __syncthreads();

    // softmax: one node per thread (tid < 64)
    if (tid < 64) {
        float* lg = sm + H_L + tid * OUTC;
        float m = lg[0];
        #pragma unroll
        for (int o = 1; o < OUTC; o++) m = fmaxf(m, lg[o]);
        float s = 0.f;
        #pragma unroll
        for (int o = 0; o < OUTC; o++) { lg[o] = expf(lg[o] - m); s += lg[o]; }
        float inv = 1.f / s;
        float* op = out + (size_t)(m0 + tid) * OUTC;
        #pragma unroll
        for (int o = 0; o < OUTC; o++) op[o] = lg[o] * inv;
    }
}

// ---------------- launch ----------------
extern "C" void kernel_launch(void* const* d_in, const int* in_sizes, int n_in,
                              void* d_out, int out_size)
{
    const float* x      = (const float*)d_in[0];
    const int*   ei     = (const int*)d_in[1];
    const float* W_in   = (const float*)d_in[2];
    const float* b_in   = (const float*)d_in[3];
    const float* cen    = (const float*)d_in[4];
    const float* wid    = (const float*)d_in[5];
    const float* Wc     = (const float*)d_in[6];
    const float* bc     = (const float*)d_in[7];
    const float* gamma  = (const float*)d_in[8];
    const float* beta   = (const float*)d_in[9];
    const float* W_head = (const float*)d_in[10];
    const float* b_head = (const float*)d_in[11];
    float* out = (float*)d_out;

    const int E = in_sizes[1] / 2;
    const int* src = ei;
    const int* dst = ei + E;

    cudaFuncSetAttribute(k_layer, cudaFuncAttributeMaxDynamicSharedMemorySize, SMEM_BYTES);
    cudaFuncSetAttribute(k_gemm_in, cudaFuncAttributeMaxDynamicSharedMemorySize, GIN_BYTES);
    cudaFuncSetAttribute(k_head, cudaFuncAttributeMaxDynamicSharedMemorySize, HEAD_BYTES);

    // CSR build (+ initial BN stat zero)
    k_zero_csr<<<(NN + 255) / 256, 256>>>();
    k_count<<<(E + 255) / 256, 256>>>(dst, E);
    k_scan<<<1, 1024>>>(E);
    k_fill<<<(E + 255) / 256, 256>>>(src, dst, E);

    // weight preprocessing (Wc + W_in merged)
    k_transAll<<<(3 * KTOT * HH + HH * HH) / 256, 256>>>(Wc, W_in);

    // input layer: h = relu(x @ W_in + b_in)  (3xBF16 MMA)
    k_gemm_in<<<NN / 128, 256, GIN_BYTES>>>(x, b_in);

    for (int l = 0; l < 3; l++) {
        k_layer<<<NN / 128, 256, SMEM_BYTES>>>(
            cen + l * RR * HH, wid + l * RR * HH, bc + l * RR * HH, l);
        k_aggregate<<<NN / 8, 256>>>(l & 1);
        k_bn_apply<<<1024, 256>>>(gamma + l * HH, beta + l * HH, l & 1);
    }

    k_head<<<NN / 64, 256, HEAD_BYTES>>>(W_head, b_head, out);
}